// round 1
// baseline (speedup 1.0000x reference)
#include <cuda_runtime.h>

#define BDIM 512
#define LL   2048
#define CC   12
#define NDIL 8
#define KK   8
#define GG   32   // _G
#define NCP  6

// XOR swizzle: conflict-free for power-of-2 strided lane access patterns
__device__ __forceinline__ int swz(int x) {
    return x ^ (((x >> 5) ^ (x >> 10)) & 31);
}

// Gather 6 channel rows at logical position x, zero outside [0, Lin)
__device__ __forceinline__ float gather6(const float* __restrict__ sm,
                                         const int roff[NCP], int x, int Lin) {
    int xc = min(max(x, 0), LL - 1);
    int a = swz(xc);
    float s = sm[roff[0] + a];
    s += sm[roff[1] + a];
    s += sm[roff[2] + a];
    s += sm[roff[3] + a];
    s += sm[roff[4] + a];
    s += sm[roff[5] + a];
    return (x >= 0 && x < Lin) ? s : 0.0f;
}

__global__ __launch_bounds__(BDIM, 1)
void hydra_kernel(const float* __restrict__ X,
                  const float* __restrict__ W,
                  const int*   __restrict__ I,
                  float* __restrict__ out)
{
    extern __shared__ float sm[];  // [0, C*L): X rows (swizzled), [C*L, 2*C*L): diff rows

    const int di = blockIdx.x;          // dilation index 0..7
    const int b  = blockIdx.y;          // batch
    const int d  = 1 << di;
    const int tid = threadIdx.x;

    const float* Xb = X + (size_t)b * CC * LL;

    // Stage X[b] and diff(X[b]) into shared memory with bank swizzle
    for (int i = tid; i < CC * LL; i += BDIM) {
        int c = i >> 11;
        int l = i & (LL - 1);
        float v  = Xb[i];
        float nv = (l < LL - 1) ? Xb[i + 1] : v;
        int a = swz(l);
        sm[c * LL + a]           = v;
        sm[CC * LL + c * LL + a] = nv - v;
    }
    __syncthreads();

    const int warp = tid >> 5;
    const int lane = tid & 31;
    const int logP = 11 - di;           // P = 2048 / d
    const int P    = LL >> di;

    // 64 tasks per block: task = diff*32 + g ; 16 warps x 4 tasks, balanced
    for (int it = 0; it < 4; ++it) {
        const int task = warp * 4 + it;
        const int diff = task >> 5;
        const int g    = task & 31;
        const int Lin  = LL - diff;     // input length == output length

        // channel-subset row offsets (into X rows or diff rows)
        const int* Ip = I + ((di * 2 + diff) * GG + g) * NCP;
        int roff[NCP];
        #pragma unroll
        for (int j = 0; j < NCP; ++j)
            roff[j] = diff * CC * LL + Ip[j] * LL;

        // 72 conv weights for this task -> registers
        const float* Wp = W + ((size_t)((di * 2 + diff) * (KK * GG) + g * KK)) * 9;
        float wreg[KK][9];
        #pragma unroll
        for (int k = 0; k < KK; ++k)
            #pragma unroll
            for (int t = 0; t < 9; ++t)
                wreg[k][t] = __ldg(Wp + k * 9 + t);

        float cm[KK];
        #pragma unroll
        for (int k = 0; k < KK; ++k) cm[k] = 0.0f;
        unsigned long long cnlo = 0ull, cnhi = 0ull;  // 4x16-bit packed min-counters each

        // phase-major enumeration: q in [lane*64, lane*64+64)
        int q = lane * 64;
        const int qend = q + 64;
        while (q < qend) {
            const int ph     = q >> logP;
            const int segEnd = min(qend, (ph + 1) << logP);
            int l = ph + (q - (ph << logP)) * d;

            // init sliding window: w[t] = inp[l + (t-4)*d]
            float w[9];
            #pragma unroll
            for (int t = 0; t < 9; ++t)
                w[t] = gather6(sm, roff, l + (t - 4) * d, Lin);

            for (; q < segEnd; ++q) {
                // k=0 dot
                float a0 = wreg[0][0] * w[0];
                #pragma unroll
                for (int t = 1; t < 9; ++t) a0 = fmaf(wreg[0][t], w[t], a0);
                float m = a0, n = a0;
                int mi = 0, ni = 0;
                // k=1..7 dots with first-occurrence argmax/argmin (matches jnp)
                #pragma unroll
                for (int k = 1; k < KK; ++k) {
                    float a = wreg[k][0] * w[0];
                    #pragma unroll
                    for (int t = 1; t < 9; ++t) a = fmaf(wreg[k][t], w[t], a);
                    if (a > m) { m = a; mi = k; }
                    if (a < n) { n = a; ni = k; }
                }

                if (l < Lin) {   // diff case: skip the phantom l == 2047
                    #pragma unroll
                    for (int k = 0; k < KK; ++k)
                        if (mi == k) cm[k] += m;
                    unsigned long long inc = 1ull << ((ni & 3) << 4);
                    if (ni < 4) cnlo += inc; else cnhi += inc;
                }

                // slide window by d: new element is inp[l + 5d]
                #pragma unroll
                for (int t = 0; t < 8; ++t) w[t] = w[t + 1];
                w[8] = gather6(sm, roff, l + 5 * d, Lin);
                l += d;
            }
        }

        // warp reduction
        #pragma unroll
        for (int k = 0; k < KK; ++k) {
            #pragma unroll
            for (int off = 16; off > 0; off >>= 1)
                cm[k] += __shfl_xor_sync(0xffffffffu, cm[k], off);
        }
        #pragma unroll
        for (int off = 16; off > 0; off >>= 1) {
            cnlo += __shfl_xor_sync(0xffffffffu, cnlo, off);
            cnhi += __shfl_xor_sync(0xffffffffu, cnhi, off);
        }

        if (lane == 0) {
            // out[b, (((di*2+diff)*2 + which)*32 + g)*8 + k]
            float* o = out + (size_t)b * (NDIL * 2 * 2 * GG * KK)
                           + ((di * 2 + diff) * 2) * (GG * KK) + g * KK;
            #pragma unroll
            for (int k = 0; k < KK; ++k) o[k] = cm[k];
            #pragma unroll
            for (int k = 0; k < 4; ++k)
                o[GG * KK + k]     = (float)((cnlo >> (k * 16)) & 0xffffull);
            #pragma unroll
            for (int k = 0; k < 4; ++k)
                o[GG * KK + 4 + k] = (float)((cnhi >> (k * 16)) & 0xffffull);
        }
    }
}

extern "C" void kernel_launch(void* const* d_in, const int* in_sizes, int n_in,
                              void* d_out, int out_size)
{
    const float* X  = (const float*)d_in[0];   // [B, 12, 2048] f32
    const float* W  = (const float*)d_in[1];   // [8, 2, 256, 1, 9] f32
    const int*   I  = (const int*)  d_in[2];   // [8, 2, 32, 6] i32
    float*       out = (float*)d_out;          // [B, 8192] f32

    const int B = in_sizes[0] / (CC * LL);
    const size_t smem = (size_t)2 * CC * LL * sizeof(float);  // 196608 B

    cudaFuncSetAttribute(hydra_kernel,
                         cudaFuncAttributeMaxDynamicSharedMemorySize, (int)smem);

    dim3 grid(NDIL, B);
    hydra_kernel<<<grid, BDIM, smem>>>(X, W, I, out);
}

// round 2
// speedup vs baseline: 1.1334x; 1.1334x over previous
#include <cuda_runtime.h>

#define BDIM 512
#define LL   2048
#define CC   12
#define NDIL 8
#define KK   8
#define GG   32
#define NCP  6

typedef unsigned long long u64;

__device__ __forceinline__ int swz(int x){ return x ^ (((x>>5)^(x>>10))&31); }

__device__ __forceinline__ u64 pack2(float lo, float hi){
  u64 r; asm("mov.b64 %0, {%1,%2};" : "=l"(r) : "f"(lo), "f"(hi)); return r;
}
__device__ __forceinline__ void unpack2(u64 v, float& lo, float& hi){
  asm("mov.b64 {%0,%1}, %2;" : "=f"(lo), "=f"(hi) : "l"(v));
}
__device__ __forceinline__ u64 ffma2(u64 a, u64 b, u64 c){
  u64 r; asm("fma.rn.f32x2 %0, %1, %2, %3;" : "=l"(r) : "l"(a), "l"(b), "l"(c)); return r;
}
__device__ __forceinline__ u64 fmul2(u64 a, u64 b){
  u64 r; asm("mul.rn.f32x2 %0, %1, %2;" : "=l"(r) : "l"(a), "l"(b)); return r;
}

// one summed tap in phase-index space; j valid iff 0 <= j < P
__device__ __forceinline__ float tapv(const float* __restrict__ sm, const int ro[6],
                                      int phase, int j, int P, int d){
  int l = (phase + j * d) & (LL - 1);
  int a = swz(l);
  float s = (sm[ro[0]+a] + sm[ro[1]+a]) + (sm[ro[2]+a] + sm[ro[3]+a])
          + (sm[ro[4]+a] + sm[ro[5]+a]);
  return ((unsigned)j < (unsigned)P) ? s : 0.0f;
}

// 8 dot products via 4 packed f32x2 accumulators
__device__ __forceinline__ void dots8(const u64 pk[36], const float w[9], float a[8]){
  u64 b = pack2(w[0], w[0]);
  u64 a0 = fmul2(pk[0], b), a1 = fmul2(pk[9], b),
      a2 = fmul2(pk[18], b), a3 = fmul2(pk[27], b);
  #pragma unroll
  for (int t = 1; t < 9; ++t){
    b  = pack2(w[t], w[t]);
    a0 = ffma2(pk[t],      b, a0);
    a1 = ffma2(pk[9 + t],  b, a1);
    a2 = ffma2(pk[18 + t], b, a2);
    a3 = ffma2(pk[27 + t], b, a3);
  }
  unpack2(a0, a[0], a[1]); unpack2(a1, a[2], a[3]);
  unpack2(a2, a[4], a[5]); unpack2(a3, a[6], a[7]);
}

// first-occurrence argmax/argmin over 8 (matches jnp tie-breaking)
__device__ __forceinline__ void chain8(const float a[8], float& m, int& mi, int& ni){
  m = a[0]; float n = a[0]; mi = 0; ni = 0;
  #pragma unroll
  for (int k = 1; k < 8; ++k){
    bool gt = a[k] > m;
    bool lt = a[k] < n;
    m = fmaxf(m, a[k]);
    n = fminf(n, a[k]);
    mi = gt ? k : mi;
    ni = lt ? k : ni;
  }
}

__global__ __launch_bounds__(BDIM, 1)
void hydra_kernel(const float* __restrict__ X,
                  const float* __restrict__ W,
                  const int*   __restrict__ I,
                  float* __restrict__ out)
{
  extern __shared__ float sm[];  // [0,C*L): X (swizzled), [C*L,2*C*L): diff (diff[2047]=0)

  const int di = blockIdx.x;
  const int b  = blockIdx.y;
  const int d  = 1 << di;
  const int tid = threadIdx.x;

  const float* Xb = X + (size_t)b * CC * LL;

  for (int i = tid; i < CC * LL; i += BDIM){
    int l = i & (LL - 1);
    float v  = Xb[i];
    float nv = (l < LL - 1) ? Xb[i + 1] : v;
    int a = swz(l);
    int c = i >> 11;
    sm[c * LL + a]           = v;
    sm[CC * LL + c * LL + a] = nv - v;
  }
  __syncthreads();

  const int warp = tid >> 5, lane = tid & 31;
  const int logP = 11 - di, P = LL >> di;
  const int SEGLEN = (P < 64) ? P : 64;   // in {16,32,64}

  for (int it = 0; it < 4; ++it){
    const int task = warp * 4 + it;
    const int diff = task >> 5, g = task & 31;

    const int* Ip = I + ((di * 2 + diff) * GG + g) * NCP;
    int ro[6];
    #pragma unroll
    for (int j = 0; j < NCP; ++j) ro[j] = diff * CC * LL + Ip[j] * LL;

    const float* Wp = W + (size_t)((di * 2 + diff) * (KK * GG) + g * KK) * 9;
    u64 pk[36];   // pk[j*9+t] = (w[2j][t], w[2j+1][t])
    #pragma unroll
    for (int j = 0; j < 4; ++j)
      #pragma unroll
      for (int t = 0; t < 9; ++t)
        pk[j * 9 + t] = pack2(__ldg(Wp + (2 * j) * 9 + t),
                              __ldg(Wp + (2 * j + 1) * 9 + t));

    float cm[8];
    #pragma unroll
    for (int k = 0; k < 8; ++k) cm[k] = 0.0f;
    u64 cnlo = 0ull, cnhi = 0ull;   // 4x16-bit packed min-counters each

    for (int s = 0; s < 64; s += SEGLEN){
      int q = lane * 64 + s;
      int phase = q >> logP;
      int ib = q & (P - 1);

      float w[9];
      #pragma unroll
      for (int t = 0; t < 9; ++t) w[t] = tapv(sm, ro, phase, ib + t - 4, P, d);

      for (int blk = 0; blk < (SEGLEN >> 3); ++blk){
        #pragma unroll
        for (int u = 0; u < 8; ++u){
          int ig = ib + blk * 8 + u;

          float a8[8]; float m; int mi, ni;
          dots8(pk, w, a8);
          chain8(a8, m, mi, ni);

          #pragma unroll
          for (int k = 0; k < 8; ++k) if (mi == k) cm[k] += m;
          u64 inc = 1ull << ((ni & 3) << 4);
          if (ni < 4) cnlo += inc; else cnhi += inc;

          float nw = tapv(sm, ro, phase, ig + 5, P, d);
          #pragma unroll
          for (int t = 0; t < 8; ++t) w[t] = w[t + 1];
          w[8] = nw;
        }
      }
    }

    // diff stream has Lout = 2047: subtract phantom position l=2047
    // (always q=2047 -> lane 31's last position; identical computation -> exact cancel)
    if (diff && lane == 31){
      float w9[9];
      #pragma unroll
      for (int t = 0; t < 9; ++t) w9[t] = tapv(sm, ro, d - 1, P - 1 + t - 4, P, d);
      float a8[8]; float m; int mi, ni;
      dots8(pk, w9, a8);
      chain8(a8, m, mi, ni);
      #pragma unroll
      for (int k = 0; k < 8; ++k) if (mi == k) cm[k] -= m;
      u64 inc = 1ull << ((ni & 3) << 4);
      if (ni < 4) cnlo -= inc; else cnhi -= inc;
    }

    // warp reduction
    #pragma unroll
    for (int k = 0; k < 8; ++k)
      #pragma unroll
      for (int off = 16; off > 0; off >>= 1)
        cm[k] += __shfl_xor_sync(0xffffffffu, cm[k], off);
    #pragma unroll
    for (int off = 16; off > 0; off >>= 1){
      cnlo += __shfl_xor_sync(0xffffffffu, cnlo, off);
      cnhi += __shfl_xor_sync(0xffffffffu, cnhi, off);
    }

    if (lane == 0){
      float* o = out + (size_t)b * (NDIL * 2 * 2 * GG * KK)
                     + ((di * 2 + diff) * 2) * (GG * KK) + g * KK;
      #pragma unroll
      for (int k = 0; k < 8; ++k) o[k] = cm[k];
      #pragma unroll
      for (int k = 0; k < 4; ++k)
        o[GG * KK + k]     = (float)((cnlo >> (k * 16)) & 0xffffull);
      #pragma unroll
      for (int k = 0; k < 4; ++k)
        o[GG * KK + 4 + k] = (float)((cnhi >> (k * 16)) & 0xffffull);
    }
  }
}

extern "C" void kernel_launch(void* const* d_in, const int* in_sizes, int n_in,
                              void* d_out, int out_size)
{
  const float* X   = (const float*)d_in[0];   // [B, 12, 2048] f32
  const float* W   = (const float*)d_in[1];   // [8, 2, 256, 1, 9] f32
  const int*   I   = (const int*)  d_in[2];   // [8, 2, 32, 6] i32
  float*       out = (float*)d_out;           // [B, 8192] f32

  const int B = in_sizes[0] / (CC * LL);
  const size_t smem = (size_t)2 * CC * LL * sizeof(float);  // 196608 B

  cudaFuncSetAttribute(hydra_kernel,
                       cudaFuncAttributeMaxDynamicSharedMemorySize, (int)smem);

  dim3 grid(NDIL, B);
  hydra_kernel<<<grid, BDIM, smem>>>(X, W, I, out);
}

// round 3
// speedup vs baseline: 1.8150x; 1.6014x over previous
#include <cuda_runtime.h>

#define BDIM 512
#define LL   2048
#define CC   12
#define NDIL 8
#define KK   8
#define GG   32
#define NCP  6

#define SCAT_OFF (2 * CC * LL)                        // 49152 floats
#define SMEM_FLOATS (SCAT_OFF + 16 * KK * 32 * 2)     // +8192 -> 57344 floats = 229376 B

typedef unsigned long long u64;

__device__ __forceinline__ int swz(int x){ return x ^ (((x>>5)^(x>>10))&31); }

__device__ __forceinline__ u64 pack2(float lo, float hi){
  u64 r; asm("mov.b64 %0, {%1,%2};" : "=l"(r) : "f"(lo), "f"(hi)); return r;
}
__device__ __forceinline__ void unpack2(u64 v, float& lo, float& hi){
  asm("mov.b64 {%0,%1}, %2;" : "=f"(lo), "=f"(hi) : "l"(v));
}
__device__ __forceinline__ u64 ffma2(u64 a, u64 b, u64 c){
  u64 r; asm("fma.rn.f32x2 %0, %1, %2, %3;" : "=l"(r) : "l"(a), "l"(b), "l"(c)); return r;
}
__device__ __forceinline__ u64 fmul2(u64 a, u64 b){
  u64 r; asm("mul.rn.f32x2 %0, %1, %2;" : "=l"(r) : "l"(a), "l"(b)); return r;
}

// one summed tap in phase-index space; j valid iff 0 <= j < P
__device__ __forceinline__ float tapv(const float* __restrict__ sm, const int ro[6],
                                      int phase, int j, int P, int d){
  int l = (phase + j * d) & (LL - 1);
  int a = swz(l);
  float s = (sm[ro[0]+a] + sm[ro[1]+a]) + (sm[ro[2]+a] + sm[ro[3]+a])
          + (sm[ro[4]+a] + sm[ro[5]+a]);
  return ((unsigned)j < (unsigned)P) ? s : 0.0f;
}

__device__ __forceinline__ void dots8(const u64 pk[36], const float w[9], float a[8]){
  u64 b = pack2(w[0], w[0]);
  u64 a0 = fmul2(pk[0], b), a1 = fmul2(pk[9], b),
      a2 = fmul2(pk[18], b), a3 = fmul2(pk[27], b);
  #pragma unroll
  for (int t = 1; t < 9; ++t){
    b  = pack2(w[t], w[t]);
    a0 = ffma2(pk[t],      b, a0);
    a1 = ffma2(pk[9 + t],  b, a1);
    a2 = ffma2(pk[18 + t], b, a2);
    a3 = ffma2(pk[27 + t], b, a3);
  }
  unpack2(a0, a[0], a[1]); unpack2(a1, a[2], a[3]);
  unpack2(a2, a[4], a[5]); unpack2(a3, a[6], a[7]);
}

// first-occurrence argmax/argmin over 8 (matches jnp tie-breaking)
__device__ __forceinline__ void chain8(const float a[8], float& m, int& mi, int& ni){
  m = a[0]; float n = a[0]; mi = 0; ni = 0;
  #pragma unroll
  for (int k = 1; k < 8; ++k){
    bool gt = a[k] > m;
    bool lt = a[k] < n;
    m = fmaxf(m, a[k]);
    n = fminf(n, a[k]);
    mi = gt ? k : mi;
    ni = lt ? k : ni;
  }
}

template<int SEG>
__device__ __forceinline__ void run_tasks(const float* __restrict__ sm,
                                          float* __restrict__ scm,
                                          float* __restrict__ scn,
                                          int di, int d, int logP, int P,
                                          const float* __restrict__ W,
                                          const int*   __restrict__ I,
                                          float* __restrict__ out,
                                          int b, int warp, int lane)
{
  for (int it = 0; it < 4; ++it){
    const int task = warp * 4 + it;
    const int diff = task >> 5, g = task & 31;

    const int* Ip = I + ((di * 2 + diff) * GG + g) * NCP;
    int ro[6];
    #pragma unroll
    for (int j = 0; j < NCP; ++j) ro[j] = diff * CC * LL + Ip[j] * LL;

    const float* Wp = W + (size_t)((di * 2 + diff) * (KK * GG) + g * KK) * 9;
    u64 pk[36];   // pk[j*9+t] = (w[2j][t], w[2j+1][t])
    #pragma unroll
    for (int j = 0; j < 4; ++j)
      #pragma unroll
      for (int t = 0; t < 9; ++t)
        pk[j * 9 + t] = pack2(__ldg(Wp + (2 * j) * 9 + t),
                              __ldg(Wp + (2 * j + 1) * 9 + t));

    // zero this warp's private scatter columns (lane-private: no sync needed)
    #pragma unroll
    for (int k = 0; k < KK; ++k){
      scm[(k << 5) + lane] = 0.0f;
      scn[(k << 5) + lane] = 0.0f;
    }

    #pragma unroll 1
    for (int s = 0; s < 64; s += SEG){
      const int q     = lane * 64 + s;
      const int phase = q >> logP;
      const int ib    = q & (P - 1);

      float w[9];
      #pragma unroll
      for (int t = 0; t < 9; ++t) w[t] = tapv(sm, ro, phase, ib + t - 4, P, d);

      #pragma unroll 1
      for (int blk = 0; blk < SEG / 8; ++blk){
        #pragma unroll
        for (int u = 0; u < 8; ++u){
          float a8[8]; float m; int mi, ni;
          dots8(pk, w, a8);
          chain8(a8, m, mi, ni);

          scm[(mi << 5) + lane] += m;      // register-indexed accumulate via smem
          scn[(ni << 5) + lane] += 1.0f;

          float nw = tapv(sm, ro, phase, ib + blk * 8 + u + 5, P, d);
          #pragma unroll
          for (int t = 0; t < 8; ++t) w[t] = w[t + 1];
          w[8] = nw;
        }
      }
    }

    // diff stream has Lout = 2047: subtract phantom position l = 2047
    // (q=2047 -> lane 31, phase=d-1, ib=P-1; identical computation -> exact cancel)
    if (diff && lane == 31){
      float w9[9];
      #pragma unroll
      for (int t = 0; t < 9; ++t) w9[t] = tapv(sm, ro, d - 1, P - 1 + t - 4, P, d);
      float a8[8]; float m; int mi, ni;
      dots8(pk, w9, a8);
      chain8(a8, m, mi, ni);
      scm[(mi << 5) + 31] -= m;
      scn[(ni << 5) + 31] -= 1.0f;
    }

    // warp reduction from smem columns + write
    float* o = out + (size_t)b * (NDIL * 2 * 2 * GG * KK)
                   + ((di * 2 + diff) * 2) * (GG * KK) + g * KK;
    #pragma unroll
    for (int k = 0; k < KK; ++k){
      float vm = scm[(k << 5) + lane];
      float vn = scn[(k << 5) + lane];
      #pragma unroll
      for (int off = 16; off > 0; off >>= 1){
        vm += __shfl_xor_sync(0xffffffffu, vm, off);
        vn += __shfl_xor_sync(0xffffffffu, vn, off);
      }
      if (lane == 0){
        o[k]           = vm;
        o[GG * KK + k] = vn;
      }
    }
  }
}

__global__ __launch_bounds__(BDIM, 1)
void hydra_kernel(const float* __restrict__ X,
                  const float* __restrict__ W,
                  const int*   __restrict__ I,
                  float* __restrict__ out)
{
  extern __shared__ float sm[];  // [0,C*L): X (swz), [C*L,2C*L): diff (diff[2047]=0), then scatter

  const int di = blockIdx.x;
  const int b  = blockIdx.y;
  const int d  = 1 << di;
  const int tid = threadIdx.x;

  const float* Xb = X + (size_t)b * CC * LL;

  for (int i = tid; i < CC * LL; i += BDIM){
    int l = i & (LL - 1);
    float v  = Xb[i];
    float nv = (l < LL - 1) ? Xb[i + 1] : v;
    int a = swz(l);
    int c = i >> 11;
    sm[c * LL + a]           = v;
    sm[CC * LL + c * LL + a] = nv - v;
  }
  __syncthreads();

  const int warp = tid >> 5, lane = tid & 31;
  const int logP = 11 - di, P = LL >> di;

  float* scm = sm + SCAT_OFF + warp * (KK * 32);
  float* scn = sm + SCAT_OFF + 16 * (KK * 32) + warp * (KK * 32);

  if (di <= 5)       run_tasks<64>(sm, scm, scn, di, d, logP, P, W, I, out, b, warp, lane);
  else if (di == 6)  run_tasks<32>(sm, scm, scn, di, d, logP, P, W, I, out, b, warp, lane);
  else               run_tasks<16>(sm, scm, scn, di, d, logP, P, W, I, out, b, warp, lane);
}

extern "C" void kernel_launch(void* const* d_in, const int* in_sizes, int n_in,
                              void* d_out, int out_size)
{
  const float* X   = (const float*)d_in[0];   // [B, 12, 2048] f32
  const float* W   = (const float*)d_in[1];   // [8, 2, 256, 1, 9] f32
  const int*   I   = (const int*)  d_in[2];   // [8, 2, 32, 6] i32
  float*       out = (float*)d_out;           // [B, 8192] f32

  const int B = in_sizes[0] / (CC * LL);
  const size_t smem = (size_t)SMEM_FLOATS * sizeof(float);   // 229376 B

  cudaFuncSetAttribute(hydra_kernel,
                       cudaFuncAttributeMaxDynamicSharedMemorySize, (int)smem);

  dim3 grid(NDIL, B);
  hydra_kernel<<<grid, BDIM, smem>>>(X, W, I, out);
}